// round 15
// baseline (speedup 1.0000x reference)
#include <cuda_runtime.h>
#include <cstdint>

#define NN_D 128
#define NN_BETA 0.001f
#define NN_EPS 1e-12f

#define MAX_N 100000
#define MAX_E 1600000
#define SCAN_BLK 1024

// Scratch (device globals: no runtime allocation allowed).
__device__ float g_support[MAX_N * NN_D];      // 51.2 MB
__device__ int   g_rowptr[MAX_N + 1];
__device__ int   g_cursor[MAX_N];
__device__ int   g_chunksum[128];
__device__ int2  g_ecolval[MAX_E];             // {col, val bits} 12.8 MB
__device__ int   g_ticket;                     // warp work-stealing counter

// ---------------------------------------------------------------------------
// Ticket reset (runs on main stream before the GEMM each launch).
// ---------------------------------------------------------------------------
__global__ void nngc_ticket_reset_kernel() { g_ticket = 0; }

// ---------------------------------------------------------------------------
// Kernel 1: support = input @ weight  (fp32, weight in smem).
// PERSISTENT, WARP-LEVEL WORK-STEALING: grid = 296 CTAs; each stages W once
// (single __syncthreads), then every WARP independently pulls 8-row tasks
// off a global atomic ticket. No barriers in the work loop -> warps overlap
// freely (the property that made the static R10 version fast), and the
// 6-vs-5-tile CTA tail becomes a ~1-task staggered drain.
// Per-task inner loop byte-identical to the proven R1 configuration.
// ---------------------------------------------------------------------------
static constexpr int GEMM_GRID = 296;   // 2 CTAs/SM x 148 SMs

__global__ __launch_bounds__(256) void nngc_gemm_kernel(
    const float* __restrict__ input,
    const float* __restrict__ weight,
    int n, int ntasks)
{
    extern __shared__ float w_s[];  // [128][128] = 64 KB
    const int tid = threadIdx.x;

    // Stage W once per CTA (coalesced float4).
    {
        const float4* wg = (const float4*)weight;
        float4* ws4 = (float4*)w_s;
#pragma unroll
        for (int i = 0; i < (NN_D * NN_D / 4) / 256; i++)
            ws4[tid + i * 256] = wg[tid + i * 256];
    }
    __syncthreads();   // w_s read-only from here on; no further barriers

    const int tx = tid & 31;   // lane: column group [tx*4, tx*4+4)

    for (;;) {
        int task;
        if (tx == 0) task = atomicAdd(&g_ticket, 1);
        task = __shfl_sync(0xFFFFFFFFu, task, 0);
        if (task >= ntasks) break;

        const int rbase = task * 8;

        bool rv[8];
#pragma unroll
        for (int i = 0; i < 8; i++) rv[i] = (rbase + i) < n;

        float acc[8][4];
#pragma unroll
        for (int i = 0; i < 8; i++)
#pragma unroll
            for (int j = 0; j < 4; j++) acc[i][j] = 0.f;

        const float* inp = input + (size_t)rbase * NN_D;

#pragma unroll 4
        for (int k = 0; k < NN_D; k += 4) {
            const float4 w0 = *(const float4*)&w_s[(k + 0) * NN_D + tx * 4];
            const float4 w1 = *(const float4*)&w_s[(k + 1) * NN_D + tx * 4];
            const float4 w2 = *(const float4*)&w_s[(k + 2) * NN_D + tx * 4];
            const float4 w3 = *(const float4*)&w_s[(k + 3) * NN_D + tx * 4];
#pragma unroll
            for (int i = 0; i < 8; i++) {
                float4 a = make_float4(0.f, 0.f, 0.f, 0.f);
                if (rv[i]) a = *(const float4*)(inp + (size_t)i * NN_D + k);
                acc[i][0] += a.x * w0.x; acc[i][1] += a.x * w0.y;
                acc[i][2] += a.x * w0.z; acc[i][3] += a.x * w0.w;
                acc[i][0] += a.y * w1.x; acc[i][1] += a.y * w1.y;
                acc[i][2] += a.y * w1.z; acc[i][3] += a.y * w1.w;
                acc[i][0] += a.z * w2.x; acc[i][1] += a.z * w2.y;
                acc[i][2] += a.z * w2.z; acc[i][3] += a.z * w2.w;
                acc[i][0] += a.w * w3.x; acc[i][1] += a.w * w3.y;
                acc[i][2] += a.w * w3.z; acc[i][3] += a.w * w3.w;
            }
        }

        float* outp = g_support + (size_t)rbase * NN_D + tx * 4;
#pragma unroll
        for (int i = 0; i < 8; i++) {
            if (rv[i]) {
                *(float4*)(outp + (size_t)i * NN_D) =
                    make_float4(acc[i][0], acc[i][1], acc[i][2], acc[i][3]);
            }
        }
    }
}

// ---------------------------------------------------------------------------
// CSR build: zero -> hist -> scan(3 kernels) -> scatter
// ---------------------------------------------------------------------------
__global__ void nngc_zero_kernel(int n)
{
    int i = blockIdx.x * 256 + threadIdx.x;
    if (i < n) g_cursor[i] = 0;
}

__global__ void nngc_hist_kernel(const int* __restrict__ erows, int E)
{
    int i = blockIdx.x * 256 + threadIdx.x;
    if (i < E) atomicAdd(&g_cursor[erows[i]], 1);
}

__global__ __launch_bounds__(SCAN_BLK) void nngc_scan1_kernel(int n)
{
    __shared__ int warpsums[32];
    const int i = blockIdx.x * SCAN_BLK + threadIdx.x;
    const int lane = threadIdx.x & 31;
    const int wid = threadIdx.x >> 5;

    int v = (i < n) ? g_cursor[i] : 0;
    int x = v;
#pragma unroll
    for (int o = 1; o < 32; o <<= 1) {
        int t = __shfl_up_sync(0xFFFFFFFFu, x, o);
        if (lane >= o) x += t;
    }
    if (lane == 31) warpsums[wid] = x;
    __syncthreads();
    if (wid == 0) {
        int s = warpsums[lane];
#pragma unroll
        for (int o = 1; o < 32; o <<= 1) {
            int t = __shfl_up_sync(0xFFFFFFFFu, s, o);
            if (lane >= o) s += t;
        }
        warpsums[lane] = s;
    }
    __syncthreads();
    const int wofs = (wid > 0) ? warpsums[wid - 1] : 0;
    if (i < n) g_rowptr[i] = wofs + x - v;  // exclusive
    if (threadIdx.x == SCAN_BLK - 1) g_chunksum[blockIdx.x] = wofs + x;
}

__global__ __launch_bounds__(128) void nngc_scan2_kernel(int nchunks, int n, int E)
{
    __shared__ int s[128];
    const int t = threadIdx.x;
    s[t] = (t < nchunks) ? g_chunksum[t] : 0;
    __syncthreads();
#pragma unroll
    for (int o = 1; o < 128; o <<= 1) {
        int v = (t >= o) ? s[t - o] : 0;
        __syncthreads();
        s[t] += v;
        __syncthreads();
    }
    if (t < nchunks) g_chunksum[t] = (t > 0) ? s[t - 1] : 0;  // exclusive
    if (t == 0) g_rowptr[n] = E;
}

__global__ __launch_bounds__(SCAN_BLK) void nngc_scan3_kernel(int n)
{
    const int i = blockIdx.x * SCAN_BLK + threadIdx.x;
    if (i < n) {
        int v = g_rowptr[i] + g_chunksum[blockIdx.x];
        g_rowptr[i] = v;
        g_cursor[i] = v;
    }
}

__global__ void nngc_scatter_kernel(
    const int* __restrict__ erows,
    const int* __restrict__ ecols,
    const float* __restrict__ evals,
    int E)
{
    int i = blockIdx.x * 256 + threadIdx.x;
    if (i < E) {
        int r = erows[i];
        int pos = atomicAdd(&g_cursor[r], 1);
        g_ecolval[pos] = make_int2(ecols[i], __float_as_int(evals[i]));
    }
}

// ---------------------------------------------------------------------------
// Fused aggregate + blend + normalize + bias. One warp per node.
// ---------------------------------------------------------------------------
__global__ __launch_bounds__(256) void nngc_agg_kernel(
    const float* __restrict__ input,
    const float* __restrict__ bias,
    float* __restrict__ out,
    int n)
{
    const int node = (blockIdx.x * 256 + threadIdx.x) >> 5;
    const int lane = threadIdx.x & 31;
    if (node >= n) return;

    const int start = __ldg(&g_rowptr[node]);
    const int end   = __ldg(&g_rowptr[node + 1]);

    const float4* sup = (const float4*)g_support;
    float4 acc = make_float4(0.f, 0.f, 0.f, 0.f);

    int e = start;
    for (; e + 1 < end; e += 2) {
        const int2 cv0 = __ldg(&g_ecolval[e]);
        const int2 cv1 = __ldg(&g_ecolval[e + 1]);
        const float v0 = __int_as_float(cv0.y);
        const float v1 = __int_as_float(cv1.y);
        const float4 s0 = sup[(size_t)cv0.x * 32 + lane];
        const float4 s1 = sup[(size_t)cv1.x * 32 + lane];
        acc.x += v0 * s0.x + v1 * s1.x;
        acc.y += v0 * s0.y + v1 * s1.y;
        acc.z += v0 * s0.z + v1 * s1.z;
        acc.w += v0 * s0.w + v1 * s1.w;
    }
    if (e < end) {
        const int2 cv = __ldg(&g_ecolval[e]);
        const float v = __int_as_float(cv.y);
        const float4 s = sup[(size_t)cv.x * 32 + lane];
        acc.x += v * s.x; acc.y += v * s.y;
        acc.z += v * s.z; acc.w += v * s.w;
    }

    const float4 x = ((const float4*)(input + (size_t)node * NN_D))[lane];
    const float omb = 1.f - NN_BETA;
    float4 o;
    o.x = NN_BETA * x.x + omb * acc.x;
    o.y = NN_BETA * x.y + omb * acc.y;
    o.z = NN_BETA * x.z + omb * acc.z;
    o.w = NN_BETA * x.w + omb * acc.w;

    float ss = o.x * o.x + o.y * o.y + o.z * o.z + o.w * o.w;
#pragma unroll
    for (int m = 16; m > 0; m >>= 1)
        ss += __shfl_xor_sync(0xFFFFFFFFu, ss, m);

    const float rn = 1.f / fmaxf(sqrtf(ss), NN_EPS);
    const float4 b = ((const float4*)bias)[lane];

    o.x = o.x * rn + b.x;
    o.y = o.y * rn + b.y;
    o.z = o.z * rn + b.z;
    o.w = o.w * rn + b.w;

    ((float4*)(out + (size_t)node * NN_D))[lane] = o;
}

// ---------------------------------------------------------------------------
// Launch: fork CSR build onto a side stream, overlap with GEMM, join for agg.
// ---------------------------------------------------------------------------
extern "C" void kernel_launch(void* const* d_in, const int* in_sizes, int n_in,
                              void* d_out, int out_size)
{
    const float* input  = (const float*)d_in[0];
    const int*   erows  = (const int*)d_in[1];
    const int*   ecols  = (const int*)d_in[2];
    const float* evals  = (const float*)d_in[3];
    const float* weight = (const float*)d_in[4];
    const float* bias   = (const float*)d_in[5];
    float* out = (float*)d_out;

    const int n = in_sizes[0] / NN_D;   // 100000
    const int E = in_sizes[1];          // 1600000

    cudaFuncSetAttribute(nngc_gemm_kernel,
                         cudaFuncAttributeMaxDynamicSharedMemorySize,
                         NN_D * NN_D * (int)sizeof(float));

    // Side stream + fork/join events (host-side creation; replay runs only the
    // captured graph, so per-call creation costs nothing in the timed loop).
    cudaStream_t s2;
    cudaStreamCreateWithFlags(&s2, cudaStreamNonBlocking);
    cudaEvent_t evFork, evJoin;
    cudaEventCreateWithFlags(&evFork, cudaEventDisableTiming);
    cudaEventCreateWithFlags(&evJoin, cudaEventDisableTiming);

    // Fork: s2 inherits the capture dependency chain of the main (legacy) stream.
    cudaEventRecord(evFork, 0);
    cudaStreamWaitEvent(s2, evFork, 0);

    // Main stream: ticket reset, then persistent warp-stealing GEMM.
    const int ntasks = (n + 7) / 8;   // 8-row tasks
    nngc_ticket_reset_kernel<<<1, 1>>>();
    nngc_gemm_kernel<<<GEMM_GRID, 256, NN_D * NN_D * sizeof(float)>>>(
        input, weight, n, ntasks);

    // Side stream: CSR build (independent of GEMM; fully hidden).
    const int nchunks = (n + SCAN_BLK - 1) / SCAN_BLK;
    nngc_zero_kernel<<<(n + 255) / 256, 256, 0, s2>>>(n);
    nngc_hist_kernel<<<(E + 255) / 256, 256, 0, s2>>>(erows, E);
    nngc_scan1_kernel<<<nchunks, SCAN_BLK, 0, s2>>>(n);
    nngc_scan2_kernel<<<1, 128, 0, s2>>>(nchunks, n, E);
    nngc_scan3_kernel<<<nchunks, SCAN_BLK, 0, s2>>>(n);
    nngc_scatter_kernel<<<(E + 255) / 256, 256, 0, s2>>>(erows, ecols, evals, E);

    // Join: main stream waits for the CSR chain, then runs fused agg+finalize.
    cudaEventRecord(evJoin, s2);
    cudaStreamWaitEvent(0, evJoin, 0);
    nngc_agg_kernel<<<(n + 7) / 8, 256>>>(input, bias, out, n);

    cudaEventDestroy(evFork);
    cudaEventDestroy(evJoin);
    cudaStreamDestroy(s2);
}

// round 16
// speedup vs baseline: 1.6034x; 1.6034x over previous
#include <cuda_runtime.h>
#include <cstdint>

#define NN_D 128
#define NN_BETA 0.001f
#define NN_EPS 1e-12f

#define MAX_N 100000
#define MAX_E 1600000
#define SCAN_BLK 1024

// Scratch (device globals: no runtime allocation allowed).
__device__ float g_support[MAX_N * NN_D];      // 51.2 MB
__device__ int   g_rowptr[MAX_N + 1];
__device__ int   g_cursor[MAX_N];
__device__ int   g_chunksum[128];
__device__ int2  g_ecolval[MAX_E];             // {col, val bits} 12.8 MB

// ---------------------------------------------------------------------------
// Kernel 1: support = input @ weight  (fp32, weight in smem).
// PERSISTENT STATIC (R10 structure): grid = 444 CTAs (3/SM via launch_bounds
// occupancy cap); each stages W once, then strides over row-tiles with NO
// barriers in the tile loop. Inner loop byte-identical to R1.
// ---------------------------------------------------------------------------
static constexpr int GEMM_MT = 64;
static constexpr int GEMM_GRID = 444;   // 3 CTAs/SM x 148 SMs

__global__ __launch_bounds__(256, 3) void nngc_gemm_kernel(
    const float* __restrict__ input,
    const float* __restrict__ weight,
    int n, int ntiles)
{
    extern __shared__ float w_s[];  // [128][128] = 64 KB
    const int tid = threadIdx.x;

    // Stage W once per CTA (coalesced float4).
    {
        const float4* wg = (const float4*)weight;
        float4* ws4 = (float4*)w_s;
#pragma unroll
        for (int i = 0; i < (NN_D * NN_D / 4) / 256; i++)
            ws4[tid + i * 256] = wg[tid + i * 256];
    }
    __syncthreads();

    const int tx = tid & 31;
    const int ty = tid >> 5;

    for (int tile = blockIdx.x; tile < ntiles; tile += GEMM_GRID) {
        const int row0 = tile * GEMM_MT;
        const int rbase = row0 + ty * 8;

        bool rv[8];
#pragma unroll
        for (int i = 0; i < 8; i++) rv[i] = (rbase + i) < n;

        float acc[8][4];
#pragma unroll
        for (int i = 0; i < 8; i++)
#pragma unroll
            for (int j = 0; j < 4; j++) acc[i][j] = 0.f;

        const float* inp = input + (size_t)rbase * NN_D;

#pragma unroll 4
        for (int k = 0; k < NN_D; k += 4) {
            const float4 w0 = *(const float4*)&w_s[(k + 0) * NN_D + tx * 4];
            const float4 w1 = *(const float4*)&w_s[(k + 1) * NN_D + tx * 4];
            const float4 w2 = *(const float4*)&w_s[(k + 2) * NN_D + tx * 4];
            const float4 w3 = *(const float4*)&w_s[(k + 3) * NN_D + tx * 4];
#pragma unroll
            for (int i = 0; i < 8; i++) {
                float4 a = make_float4(0.f, 0.f, 0.f, 0.f);
                if (rv[i]) a = *(const float4*)(inp + (size_t)i * NN_D + k);
                acc[i][0] += a.x * w0.x; acc[i][1] += a.x * w0.y;
                acc[i][2] += a.x * w0.z; acc[i][3] += a.x * w0.w;
                acc[i][0] += a.y * w1.x; acc[i][1] += a.y * w1.y;
                acc[i][2] += a.y * w1.z; acc[i][3] += a.y * w1.w;
                acc[i][0] += a.z * w2.x; acc[i][1] += a.z * w2.y;
                acc[i][2] += a.z * w2.z; acc[i][3] += a.z * w2.w;
                acc[i][0] += a.w * w3.x; acc[i][1] += a.w * w3.y;
                acc[i][2] += a.w * w3.z; acc[i][3] += a.w * w3.w;
            }
        }

        float* outp = g_support + (size_t)rbase * NN_D + tx * 4;
#pragma unroll
        for (int i = 0; i < 8; i++) {
            if (rv[i]) {
                *(float4*)(outp + (size_t)i * NN_D) =
                    make_float4(acc[i][0], acc[i][1], acc[i][2], acc[i][3]);
            }
        }
    }
}

// ---------------------------------------------------------------------------
// CSR build: zero -> hist -> scan(3 kernels) -> scatter
// ---------------------------------------------------------------------------
__global__ void nngc_zero_kernel(int n)
{
    int i = blockIdx.x * 256 + threadIdx.x;
    if (i < n) g_cursor[i] = 0;
}

__global__ void nngc_hist_kernel(const int* __restrict__ erows, int E)
{
    int i = blockIdx.x * 256 + threadIdx.x;
    if (i < E) atomicAdd(&g_cursor[erows[i]], 1);
}

__global__ __launch_bounds__(SCAN_BLK) void nngc_scan1_kernel(int n)
{
    __shared__ int warpsums[32];
    const int i = blockIdx.x * SCAN_BLK + threadIdx.x;
    const int lane = threadIdx.x & 31;
    const int wid = threadIdx.x >> 5;

    int v = (i < n) ? g_cursor[i] : 0;
    int x = v;
#pragma unroll
    for (int o = 1; o < 32; o <<= 1) {
        int t = __shfl_up_sync(0xFFFFFFFFu, x, o);
        if (lane >= o) x += t;
    }
    if (lane == 31) warpsums[wid] = x;
    __syncthreads();
    if (wid == 0) {
        int s = warpsums[lane];
#pragma unroll
        for (int o = 1; o < 32; o <<= 1) {
            int t = __shfl_up_sync(0xFFFFFFFFu, s, o);
            if (lane >= o) s += t;
        }
        warpsums[lane] = s;
    }
    __syncthreads();
    const int wofs = (wid > 0) ? warpsums[wid - 1] : 0;
    if (i < n) g_rowptr[i] = wofs + x - v;  // exclusive
    if (threadIdx.x == SCAN_BLK - 1) g_chunksum[blockIdx.x] = wofs + x;
}

__global__ __launch_bounds__(128) void nngc_scan2_kernel(int nchunks, int n, int E)
{
    __shared__ int s[128];
    const int t = threadIdx.x;
    s[t] = (t < nchunks) ? g_chunksum[t] : 0;
    __syncthreads();
#pragma unroll
    for (int o = 1; o < 128; o <<= 1) {
        int v = (t >= o) ? s[t - o] : 0;
        __syncthreads();
        s[t] += v;
        __syncthreads();
    }
    if (t < nchunks) g_chunksum[t] = (t > 0) ? s[t - 1] : 0;  // exclusive
    if (t == 0) g_rowptr[n] = E;
}

__global__ __launch_bounds__(SCAN_BLK) void nngc_scan3_kernel(int n)
{
    const int i = blockIdx.x * SCAN_BLK + threadIdx.x;
    if (i < n) {
        int v = g_rowptr[i] + g_chunksum[blockIdx.x];
        g_rowptr[i] = v;
        g_cursor[i] = v;
    }
}

__global__ void nngc_scatter_kernel(
    const int* __restrict__ erows,
    const int* __restrict__ ecols,
    const float* __restrict__ evals,
    int E)
{
    int i = blockIdx.x * 256 + threadIdx.x;
    if (i < E) {
        int r = erows[i];
        int pos = atomicAdd(&g_cursor[r], 1);
        g_ecolval[pos] = make_int2(ecols[i], __float_as_int(evals[i]));
    }
}

// ---------------------------------------------------------------------------
// Fused aggregate + blend + normalize + bias. One warp per node.
// ---------------------------------------------------------------------------
__global__ __launch_bounds__(256) void nngc_agg_kernel(
    const float* __restrict__ input,
    const float* __restrict__ bias,
    float* __restrict__ out,
    int n)
{
    const int node = (blockIdx.x * 256 + threadIdx.x) >> 5;
    const int lane = threadIdx.x & 31;
    if (node >= n) return;

    const int start = __ldg(&g_rowptr[node]);
    const int end   = __ldg(&g_rowptr[node + 1]);

    const float4* sup = (const float4*)g_support;
    float4 acc = make_float4(0.f, 0.f, 0.f, 0.f);

    int e = start;
    for (; e + 1 < end; e += 2) {
        const int2 cv0 = __ldg(&g_ecolval[e]);
        const int2 cv1 = __ldg(&g_ecolval[e + 1]);
        const float v0 = __int_as_float(cv0.y);
        const float v1 = __int_as_float(cv1.y);
        const float4 s0 = sup[(size_t)cv0.x * 32 + lane];
        const float4 s1 = sup[(size_t)cv1.x * 32 + lane];
        acc.x += v0 * s0.x + v1 * s1.x;
        acc.y += v0 * s0.y + v1 * s1.y;
        acc.z += v0 * s0.z + v1 * s1.z;
        acc.w += v0 * s0.w + v1 * s1.w;
    }
    if (e < end) {
        const int2 cv = __ldg(&g_ecolval[e]);
        const float v = __int_as_float(cv.y);
        const float4 s = sup[(size_t)cv.x * 32 + lane];
        acc.x += v * s.x; acc.y += v * s.y;
        acc.z += v * s.z; acc.w += v * s.w;
    }

    const float4 x = ((const float4*)(input + (size_t)node * NN_D))[lane];
    const float omb = 1.f - NN_BETA;
    float4 o;
    o.x = NN_BETA * x.x + omb * acc.x;
    o.y = NN_BETA * x.y + omb * acc.y;
    o.z = NN_BETA * x.z + omb * acc.z;
    o.w = NN_BETA * x.w + omb * acc.w;

    float ss = o.x * o.x + o.y * o.y + o.z * o.z + o.w * o.w;
#pragma unroll
    for (int m = 16; m > 0; m >>= 1)
        ss += __shfl_xor_sync(0xFFFFFFFFu, ss, m);

    const float rn = 1.f / fmaxf(sqrtf(ss), NN_EPS);
    const float4 b = ((const float4*)bias)[lane];

    o.x = o.x * rn + b.x;
    o.y = o.y * rn + b.y;
    o.z = o.z * rn + b.z;
    o.w = o.w * rn + b.w;

    ((float4*)(out + (size_t)node * NN_D))[lane] = o;
}

// ---------------------------------------------------------------------------
// Launch: fork CSR build onto a side stream, overlap with GEMM, join for agg.
// ---------------------------------------------------------------------------
extern "C" void kernel_launch(void* const* d_in, const int* in_sizes, int n_in,
                              void* d_out, int out_size)
{
    const float* input  = (const float*)d_in[0];
    const int*   erows  = (const int*)d_in[1];
    const int*   ecols  = (const int*)d_in[2];
    const float* evals  = (const float*)d_in[3];
    const float* weight = (const float*)d_in[4];
    const float* bias   = (const float*)d_in[5];
    float* out = (float*)d_out;

    const int n = in_sizes[0] / NN_D;   // 100000
    const int E = in_sizes[1];          // 1600000

    cudaFuncSetAttribute(nngc_gemm_kernel,
                         cudaFuncAttributeMaxDynamicSharedMemorySize,
                         NN_D * NN_D * (int)sizeof(float));

    // Side stream + fork/join events (host-side creation; replay runs only the
    // captured graph, so per-call creation costs nothing in the timed loop).
    cudaStream_t s2;
    cudaStreamCreateWithFlags(&s2, cudaStreamNonBlocking);
    cudaEvent_t evFork, evJoin;
    cudaEventCreateWithFlags(&evFork, cudaEventDisableTiming);
    cudaEventCreateWithFlags(&evJoin, cudaEventDisableTiming);

    // Fork: s2 inherits the capture dependency chain of the main (legacy) stream.
    cudaEventRecord(evFork, 0);
    cudaStreamWaitEvent(s2, evFork, 0);

    // Main stream: persistent static GEMM at 3 CTAs/SM.
    const int ntiles = (n + GEMM_MT - 1) / GEMM_MT;
    nngc_gemm_kernel<<<GEMM_GRID, 256, NN_D * NN_D * sizeof(float)>>>(
        input, weight, n, ntiles);

    // Side stream: CSR build (independent of GEMM; fully hidden).
    const int nchunks = (n + SCAN_BLK - 1) / SCAN_BLK;
    nngc_zero_kernel<<<(n + 255) / 256, 256, 0, s2>>>(n);
    nngc_hist_kernel<<<(E + 255) / 256, 256, 0, s2>>>(erows, E);
    nngc_scan1_kernel<<<nchunks, SCAN_BLK, 0, s2>>>(n);
    nngc_scan2_kernel<<<1, 128, 0, s2>>>(nchunks, n, E);
    nngc_scan3_kernel<<<nchunks, SCAN_BLK, 0, s2>>>(n);
    nngc_scatter_kernel<<<(E + 255) / 256, 256, 0, s2>>>(erows, ecols, evals, E);

    // Join: main stream waits for the CSR chain, then runs fused agg+finalize.
    cudaEventRecord(evJoin, s2);
    cudaStreamWaitEvent(0, evJoin, 0);
    nngc_agg_kernel<<<(n + 7) / 8, 256>>>(input, bias, out, n);

    cudaEventDestroy(evFork);
    cudaEventDestroy(evJoin);
    cudaStreamDestroy(s2);
}